// round 12
// baseline (speedup 1.0000x reference)
#include <cuda_runtime.h>
#include <cuda_bf16.h>
#include <math.h>

#define Bsz   512
#define Tsz   256
#define Fsz   128
#define Hsz   512
#define FFsz  1024
#define OUTsz 64
#define H3    (3 * Hsz)
#define BT    (Bsz * Tsz)
#define PADV  (-999.0f)
#define GW_WORDS 24576   // per-blkn W slice (tf32): 32kt*3g*2jsl*(32lane*4w) = 96KB

// ---------------- scratch ----------------
__device__ float g_GI[(size_t)BT * H3];
__device__ float g_ffin[(size_t)BT * Hsz];
__device__ float g_hid[(size_t)BT * FFsz];
// fragment-major h (tf32 words, k-mod-4 permuted): [pp][m][ktgrp(32)][16 words]
__device__ unsigned g_hfrag[2][(size_t)Bsz * 32 * 16];
__device__ unsigned g_wfrag[32 * GW_WORDS];
__device__ unsigned g_barg[4 * 32];   // per-m-group barrier counters (128B spaced)

// ---------------- helpers ----------------
__device__ __forceinline__ unsigned long long pack2(float x, float y) {
    unsigned long long r;
    asm("mov.b64 %0,{%1,%2};" : "=l"(r) : "f"(x), "f"(y));
    return r;
}
__device__ __forceinline__ void fma2(unsigned long long& d, unsigned long long a,
                                     unsigned long long b) {
    asm("fma.rn.f32x2 %0,%1,%2,%0;" : "+l"(d) : "l"(a), "l"(b));
}
__device__ __forceinline__ void unpack2(unsigned long long v, float& x, float& y) {
    asm("mov.b64 {%0,%1},%2;" : "=f"(x), "=f"(y) : "l"(v));
}
__device__ __forceinline__ void mma_bf16(float* d, unsigned a0, unsigned a1,
                                         unsigned a2, unsigned a3,
                                         unsigned b0, unsigned b1) {
    asm volatile(
        "mma.sync.aligned.m16n8k16.row.col.f32.bf16.bf16.f32 "
        "{%0,%1,%2,%3},{%4,%5,%6,%7},{%8,%9},{%0,%1,%2,%3};"
        : "+f"(d[0]), "+f"(d[1]), "+f"(d[2]), "+f"(d[3])
        : "r"(a0), "r"(a1), "r"(a2), "r"(a3), "r"(b0), "r"(b1));
}
__device__ __forceinline__ void mma_tf32(float* d, unsigned a0, unsigned a1,
                                         unsigned a2, unsigned a3,
                                         unsigned b0, unsigned b1) {
    asm volatile(
        "mma.sync.aligned.m16n8k8.row.col.f32.tf32.tf32.f32 "
        "{%0,%1,%2,%3},{%4,%5,%6,%7},{%8,%9},{%0,%1,%2,%3};"
        : "+f"(d[0]), "+f"(d[1]), "+f"(d[2]), "+f"(d[3])
        : "r"(a0), "r"(a1), "r"(a2), "r"(a3), "r"(b0), "r"(b1));
}
__device__ __forceinline__ unsigned bf2pack(float x, float y) {
    __nv_bfloat162 v = __floats2bfloat162_rn(x, y);
    return *(unsigned*)&v;
}
__device__ __forceinline__ void bfunpack(unsigned p, float& x, float& y) {
    __nv_bfloat162 v = *(__nv_bfloat162*)&p;
    x = __bfloat162float(__low2bfloat16(v));
    y = __bfloat162float(__high2bfloat16(v));
}
__device__ __forceinline__ void split2(float x, float y, unsigned& hi, unsigned& lo) {
    hi = bf2pack(x, y);
    float hx, hy;
    bfunpack(hi, hx, hy);
    lo = bf2pack(x - hx, y - hy);
}
__device__ __forceinline__ unsigned tf32r(float x) {
    unsigned r;
    asm("cvt.rna.tf32.f32 %0,%1;" : "=r"(r) : "f"(x));
    return r;
}

// ---------------- init ----------------
__global__ void init_kernel() {
    int i = blockIdx.x * blockDim.x + threadIdx.x;
    int tot = Bsz * 32 * 16;
    if (i < tot) g_hfrag[0][i] = 0u;
    if (i < 4 * 32) g_barg[i] = 0u;
}

// ---------------- W_hh -> tf32 fragment layout ----------------
// [blkn(32)][kt(32)][g(3)][jsl(2)][lane(32)][4w]; word q = W[n][kt*16+thr+4q]
__global__ void wprep_kernel(const float* __restrict__ W_hh) {
    int idx = blockIdx.x * blockDim.x + threadIdx.x;
    if (idx >= 32 * 32 * 3 * 2 * 32) return;
    int lane = idx & 31;
    int r = idx >> 5;
    int jsl = r & 1; r >>= 1;
    int g = r % 3;   r /= 3;
    int kt = r & 31;
    int blkn = r >> 5;          // 0..31
    int grp = lane >> 2, thr = lane & 3;

    int n_row = g * Hsz + blkn * 16 + jsl * 8 + grp;
    const float* src = &W_hh[(size_t)n_row * Hsz + kt * 16];
    unsigned* dst = &g_wfrag[(size_t)((((blkn * 32 + kt) * 3 + g) * 2 + jsl)) * 128 + lane * 4];
#pragma unroll
    for (int q = 0; q < 4; q++) dst[q] = tf32r(src[thr + 4 * q]);
}

// ---------------- bf16-split MMA GEMM (R8/R11 version; verified) ----------------
template <int KDIM, int NDIM, bool BTRANS, bool RELU, bool SKIP>
__global__ __launch_bounds__(256) void hgemm(const float* __restrict__ A,
                                             const float* __restrict__ Bm,
                                             const float* __restrict__ bias,
                                             float* __restrict__ C,
                                             const int* __restrict__ seq) {
    const int m0 = blockIdx.x * 128;
    const int n0 = blockIdx.y * 128;
    if (SKIP) {
        int b = m0 / Tsz, t0 = m0 % Tsz;
        if (t0 >= seq[b]) return;
    }
    __shared__ __align__(16) unsigned sA[4096];
    __shared__ __align__(16) unsigned sB[4096];

    const int tid = threadIdx.x;
    const int lane = tid & 31;
    const int wid = tid >> 5;
    const int mw = wid >> 2;
    const int nw = wid & 3;
    const int grp = lane >> 2, thr = lane & 3;

    float acc[4][4][4];
#pragma unroll
    for (int i = 0; i < 4; i++)
#pragma unroll
        for (int j = 0; j < 4; j++)
#pragma unroll
            for (int c = 0; c < 4; c++) acc[i][j][c] = 0.0f;

    for (int k0 = 0; k0 < KDIM; k0 += 32) {
        if (k0 > 0) __syncthreads();
#pragma unroll
        for (int it = 0; it < 8; it++) {
            int fid = tid + it * 256;
            int row = fid >> 4, cp = fid & 15;
            int q = cp >> 3, rem = cp & 7;
            int fthr = rem & 3, whalf = rem >> 2;
            int mt = row >> 4, rin = row & 15;
            int fgrp = rin & 7, wlow = rin >> 3;
            int w = whalf * 2 + wlow;
            int flane = fgrp * 4 + fthr;
            float2 v = *(const float2*)&A[(size_t)(m0 + row) * KDIM + k0 + cp * 2];
            unsigned hi, lo;
            split2(v.x, v.y, hi, lo);
            int base = ((q * 8 + mt) * 2) * 128 + flane * 4 + w;
            sA[base] = hi;
            sA[base + 128] = lo;
        }
        if (BTRANS) {
#pragma unroll
            for (int it = 0; it < 8; it++) {
                int fid = tid + it * 256;
                int row = fid >> 4, cp = fid & 15;
                int q = cp >> 3, rem = cp & 7;
                int fthr = rem & 3, w = rem >> 2;
                int nt = row >> 3, fgrp = row & 7;
                int flane = fgrp * 4 + fthr;
                float2 v = *(const float2*)&Bm[(size_t)(n0 + row) * KDIM + k0 + cp * 2];
                unsigned hi, lo;
                split2(v.x, v.y, hi, lo);
                int base = ((q * 16 + nt) * 2) * 64 + flane * 2 + w;
                sB[base] = hi;
                sB[base + 64] = lo;
            }
        } else {
#pragma unroll
            for (int it = 0; it < 2; it++) {
                int uid = tid + it * 256;
                int kp = uid >> 5, n4 = uid & 31;
                int n = n4 * 4;
                float4 r0 = *(const float4*)&Bm[(size_t)(k0 + kp * 2) * NDIM + n0 + n];
                float4 r1 = *(const float4*)&Bm[(size_t)(k0 + kp * 2 + 1) * NDIM + n0 + n];
                int q = kp >> 3, p = kp & 7;
                int fthr = p & 3, w = p >> 2;
                float e0[4] = {r0.x, r0.y, r0.z, r0.w};
                float e1[4] = {r1.x, r1.y, r1.z, r1.w};
#pragma unroll
                for (int e = 0; e < 4; e++) {
                    int nn = n + e;
                    int nt = nn >> 3, fgrp = nn & 7;
                    int flane = fgrp * 4 + fthr;
                    unsigned hi, lo;
                    split2(e0[e], e1[e], hi, lo);
                    int base = ((q * 16 + nt) * 2) * 64 + flane * 2 + w;
                    sB[base] = hi;
                    sB[base + 64] = lo;
                }
            }
        }
        __syncthreads();

#pragma unroll
        for (int q = 0; q < 2; q++) {
            uint2 bh[4], bl[4];
#pragma unroll
            for (int j = 0; j < 4; j++) {
                int base = ((q * 16 + nw * 4 + j) * 2) * 64 + lane * 2;
                bh[j] = *(const uint2*)&sB[base];
                bl[j] = *(const uint2*)&sB[base + 64];
            }
#pragma unroll
            for (int i = 0; i < 4; i++) {
                int base = ((q * 8 + mw * 4 + i) * 2) * 128 + lane * 4;
                uint4 ah = *(const uint4*)&sA[base];
                uint4 al = *(const uint4*)&sA[base + 128];
#pragma unroll
                for (int j = 0; j < 4; j++) {
                    mma_bf16(acc[i][j], ah.x, ah.y, ah.z, ah.w, bh[j].x, bh[j].y);
                    mma_bf16(acc[i][j], ah.x, ah.y, ah.z, ah.w, bl[j].x, bl[j].y);
                    mma_bf16(acc[i][j], al.x, al.y, al.z, al.w, bh[j].x, bh[j].y);
                }
            }
        }
    }

#pragma unroll
    for (int i = 0; i < 4; i++) {
        const int r0 = m0 + (mw * 4 + i) * 16 + grp;
#pragma unroll
        for (int j = 0; j < 4; j++) {
            const int col = n0 + (nw * 4 + j) * 8 + thr * 2;
            const float b0 = bias[col], b1 = bias[col + 1];
            float o0 = acc[i][j][0] + b0, o1 = acc[i][j][1] + b1;
            float o2 = acc[i][j][2] + b0, o3 = acc[i][j][3] + b1;
            if (RELU) {
                o0 = fmaxf(o0, 0.f); o1 = fmaxf(o1, 0.f);
                o2 = fmaxf(o2, 0.f); o3 = fmaxf(o3, 0.f);
            }
            *(float2*)&C[(size_t)r0 * NDIM + col] = make_float2(o0, o1);
            *(float2*)&C[(size_t)(r0 + 8) * NDIM + col] = make_float2(o2, o3);
        }
    }
}

// ---------------- persistent tf32 GRU v4: m128 x n16 blocks ---------------------
// Grid=128: mgrp = bid>>5 (128 batch rows), blkn = bid&31 (16 hidden cols).
// 8 warps = 4 m-warps (m32) x 2 jsl (n8). Per warp per kt: 3 LDS.128 B (halved),
// 4 LDG.128 A, 12 mma. Release/acquire barrier; ffin+GI overlap the wait.
__global__ __launch_bounds__(256, 1) void gru_mma(
    const float* __restrict__ GI, const float* __restrict__ b_hh,
    const int* __restrict__ seq, float* __restrict__ ffin) {
    extern __shared__ unsigned Bw[];   // [kt][g][jsl][lane*4] = 96KB

    const int tid = threadIdx.x;
    const int lane = tid & 31;
    const int wid  = tid >> 5;
    const int mw = wid & 3, jsl = wid >> 2;
    const int grp = lane >> 2, thr = lane & 3;
    const int mgrp = blockIdx.x >> 5;
    const int m0 = mgrp * 128;
    const int blkn = blockIdx.x & 31;
    const int hb = blkn * 16;
    const int c = hb + jsl * 8 + thr * 2;
    // kword(jsl*8 + thr*2): permuted word index for h-frag stores
    const int wst = (thr & 1) * 8 + jsl * 2 + (thr >> 1);

    // load 96KB W slice into persistent smem
    {
        const uint4* src = (const uint4*)&g_wfrag[(size_t)blkn * GW_WORDS];
        uint4* dst = (uint4*)Bw;
        for (int i = tid; i < GW_WORDS / 4; i += 256) dst[i] = src[i];
    }

    int mrow[4], slen[4];
#pragma unroll
    for (int p = 0; p < 4; p++) {
        mrow[p] = m0 + mw * 32 + p * 8 + grp;
        slen[p] = seq[mrow[p]];
    }

    float2 bh[3];
#pragma unroll
    for (int g = 0; g < 3; g++) bh[g] = *(const float2*)&b_hh[g * Hsz + c];

    float hreg[4][2];
#pragma unroll
    for (int p = 0; p < 4; p++) { hreg[p][0] = 0.0f; hreg[p][1] = 0.0f; }

    // GI prefetch for t=0
    float2 pgi[4][3];
#pragma unroll
    for (int p = 0; p < 4; p++) {
        const size_t gib = ((size_t)mrow[p] * Tsz + 0) * (size_t)H3;
#pragma unroll
        for (int g = 0; g < 3; g++)
            pgi[p][g] = *(const float2*)&GI[gib + g * Hsz + c];
    }

    unsigned* ctr = &g_barg[mgrp * 32];

    __syncthreads();

    for (int t = 0; t < Tsz; ++t) {
        const int pp = t & 1;
        const unsigned* __restrict__ Af = g_hfrag[pp];
        unsigned* __restrict__ Ao = g_hfrag[pp ^ 1];

        float acc[2][3][4];
#pragma unroll
        for (int q = 0; q < 2; q++)
#pragma unroll
            for (int g = 0; g < 3; g++)
#pragma unroll
                for (int cc = 0; cc < 4; cc++) acc[q][g][cc] = 0.0f;

        // distance-2 A prefetch: 4 rows
        uint4 pfA[2][4];
#pragma unroll
        for (int b = 0; b < 2; b++)
#pragma unroll
            for (int p = 0; p < 4; p++)
                pfA[b][p] = __ldcg((const uint4*)&Af[((size_t)mrow[p] * 32 + b) * 16 + thr * 4]);

#pragma unroll 4
        for (int kt = 0; kt < 32; ++kt) {
            const uint4 a0 = pfA[kt & 1][0];
            const uint4 a1 = pfA[kt & 1][1];
            const uint4 a2 = pfA[kt & 1][2];
            const uint4 a3 = pfA[kt & 1][3];
            if (kt < 30) {
#pragma unroll
                for (int p = 0; p < 4; p++)
                    pfA[kt & 1][p] = __ldcg((const uint4*)&Af[((size_t)mrow[p] * 32 + kt + 2) * 16 + thr * 4]);
            }
#pragma unroll
            for (int g = 0; g < 3; g++) {
                const uint4 bb = *(const uint4*)&Bw[((kt * 3 + g) * 2 + jsl) * 128 + lane * 4];
                mma_tf32(acc[0][g], a0.x, a1.x, a0.y, a1.y, bb.x, bb.y);
                mma_tf32(acc[0][g], a0.z, a1.z, a0.w, a1.w, bb.z, bb.w);
                mma_tf32(acc[1][g], a2.x, a3.x, a2.y, a3.y, bb.x, bb.y);
                mma_tf32(acc[1][g], a2.z, a3.z, a2.w, a3.w, bb.z, bb.w);
            }
        }

        // ---- epilogue: gates + state update + h-frag stores ----
#pragma unroll
        for (int p = 0; p < 4; p++) {
            const int q = p >> 1;
            const int ai = (p & 1) * 2;
            if (t < slen[p]) {
                const float ghr0 = acc[q][0][ai] + bh[0].x;
                const float ghr1 = acc[q][0][ai + 1] + bh[0].y;
                const float ghz0 = acc[q][1][ai] + bh[1].x;
                const float ghz1 = acc[q][1][ai + 1] + bh[1].y;
                const float ghn0 = acc[q][2][ai] + bh[2].x;
                const float ghn1 = acc[q][2][ai + 1] + bh[2].y;
                const float r0 = __fdividef(1.0f, 1.0f + __expf(-(pgi[p][0].x + ghr0)));
                const float r1 = __fdividef(1.0f, 1.0f + __expf(-(pgi[p][0].y + ghr1)));
                const float z0 = __fdividef(1.0f, 1.0f + __expf(-(pgi[p][1].x + ghz0)));
                const float z1 = __fdividef(1.0f, 1.0f + __expf(-(pgi[p][1].y + ghz1)));
                const float n0v = tanhf(pgi[p][2].x + r0 * ghn0);
                const float n1v = tanhf(pgi[p][2].y + r1 * ghn1);
                hreg[p][0] = (1.0f - z0) * n0v + z0 * hreg[p][0];
                hreg[p][1] = (1.0f - z1) * n1v + z1 * hreg[p][1];
            }
            const size_t ab = ((size_t)mrow[p] * 32 + blkn) * 16;
            Ao[ab + wst]     = tf32r(hreg[p][0]);
            Ao[ab + wst + 4] = tf32r(hreg[p][1]);
        }

        if (t < Tsz - 1) {
            __syncthreads();   // all h-frag stores issued block-wide
            if (tid == 0) {
                asm volatile("red.release.gpu.global.add.u32 [%0], 1;"
                             :: "l"(ctr) : "memory");
            }
            // overlap with barrier wait: ffin stores + GI prefetch for t+1
#pragma unroll
            for (int p = 0; p < 4; p++) {
                const size_t bt = (size_t)mrow[p] * Tsz + t;
                float2 fv = (t < slen[p]) ? make_float2(hreg[p][0], hreg[p][1])
                                          : make_float2(0.0f, 0.0f);
                *(float2*)&ffin[bt * (size_t)Hsz + c] = fv;
            }
#pragma unroll
            for (int p = 0; p < 4; p++) {
                const size_t gib = ((size_t)mrow[p] * Tsz + (t + 1)) * (size_t)H3;
#pragma unroll
                for (int g = 0; g < 3; g++)
                    pgi[p][g] = *(const float2*)&GI[gib + g * Hsz + c];
            }
            if (tid == 0) {
                const unsigned target = 32u * (unsigned)(t + 1);
                unsigned v;
                while (true) {
                    asm volatile("ld.acquire.gpu.global.u32 %0, [%1];"
                                 : "=r"(v) : "l"(ctr) : "memory");
                    if (v >= target) break;
                    __nanosleep(32);
                }
            }
            __syncthreads();
        } else {
#pragma unroll
            for (int p = 0; p < 4; p++) {
                const size_t bt = (size_t)mrow[p] * Tsz + t;
                float2 fv = (t < slen[p]) ? make_float2(hreg[p][0], hreg[p][1])
                                          : make_float2(0.0f, 0.0f);
                *(float2*)&ffin[bt * (size_t)Hsz + c] = fv;
            }
        }
    }
}

// ---------------- output GEMM: Y = hid @ W2 + b2, PAD-masked ---------------------
__global__ __launch_bounds__(256) void out_gemm_kernel(const float* __restrict__ W2,
                                                       const float* __restrict__ b2,
                                                       const int* __restrict__ seq,
                                                       float* __restrict__ Y) {
    const int m0 = blockIdx.x * 128;
    const int b  = m0 / Tsz;
    const int t0 = m0 % Tsz;
    const int tid = threadIdx.x;
    const int slen = seq[b];
    if (t0 >= slen) {
        float4 pv = make_float4(PADV, PADV, PADV, PADV);
#pragma unroll
        for (int l = 0; l < 8; l++) {
            int idx = tid + l * 256;
            *(float4*)&Y[(size_t)(m0 + (idx >> 4)) * OUTsz + (idx & 15) * 4] = pv;
        }
        return;
    }
    __shared__ float As[32][128];
    __shared__ float Bs[32][64];
    const int tx = tid % 16, ty = tid / 16;
    const int row0 = ty * 8, col0 = tx * 4;
    unsigned long long acc[8][2];
#pragma unroll
    for (int i = 0; i < 8; i++) { acc[i][0] = 0ULL; acc[i][1] = 0ULL; }

    for (int k0 = 0; k0 < FFsz; k0 += 32) {
#pragma unroll
        for (int l = 0; l < 4; l++) {
            int idx = tid + l * 256;
            int r = idx >> 3, c4 = (idx & 7) * 4;
            float4 v = *(const float4*)&g_hid[(size_t)(m0 + r) * FFsz + k0 + c4];
            As[c4 + 0][r] = v.x; As[c4 + 1][r] = v.y;
            As[c4 + 2][r] = v.z; As[c4 + 3][r] = v.w;
        }
#pragma unroll
        for (int l = 0; l < 2; l++) {
            int idx = tid + l * 256;
            int k = idx >> 4, c4 = (idx & 15) * 4;
            *(float4*)&Bs[k][c4] = *(const float4*)&W2[(size_t)(k0 + k) * OUTsz + c4];
        }
        __syncthreads();
#pragma unroll
        for (int k = 0; k < 32; k++) {
            float4 a0 = *(const float4*)&As[k][row0];
            float4 a1 = *(const float4*)&As[k][row0 + 4];
            unsigned long long b0 = *(const unsigned long long*)&Bs[k][col0];
            unsigned long long b1 = *(const unsigned long long*)&Bs[k][col0 + 2];
            float av[8] = {a0.x, a0.y, a0.z, a0.w, a1.x, a1.y, a1.z, a1.w};
#pragma unroll
            for (int i = 0; i < 8; i++) {
                unsigned long long ad = pack2(av[i], av[i]);
                fma2(acc[i][0], ad, b0);
                fma2(acc[i][1], ad, b1);
            }
        }
        __syncthreads();
    }
#pragma unroll
    for (int i = 0; i < 8; i++) {
        int m = m0 + row0 + i;
        int t = t0 + row0 + i;
        float o[4];
        unpack2(acc[i][0], o[0], o[1]);
        unpack2(acc[i][1], o[2], o[3]);
        float4 v;
        if (t < slen) {
            v = make_float4(o[0] + b2[col0 + 0], o[1] + b2[col0 + 1],
                            o[2] + b2[col0 + 2], o[3] + b2[col0 + 3]);
        } else {
            v = make_float4(PADV, PADV, PADV, PADV);
        }
        *(float4*)&Y[(size_t)m * OUTsz + col0] = v;
    }
}

// ---------------- launch ----------------
extern "C" void kernel_launch(void* const* d_in, const int* in_sizes, int n_in,
                              void* d_out, int out_size) {
    (void)in_sizes; (void)n_in; (void)out_size;
    const float* x    = (const float*)d_in[0];
    const int*   seq  = (const int*)d_in[1];
    const float* W_ih = (const float*)d_in[2];
    const float* W_hh = (const float*)d_in[3];
    const float* b_ih = (const float*)d_in[4];
    const float* b_hh = (const float*)d_in[5];
    const float* W1   = (const float*)d_in[6];
    const float* b1   = (const float*)d_in[7];
    const float* W2   = (const float*)d_in[8];
    const float* b2   = (const float*)d_in[9];
    float* Y = (float*)d_out;

    float *pGI = nullptr, *pFF = nullptr, *pHID = nullptr;
    cudaGetSymbolAddress((void**)&pGI, g_GI);
    cudaGetSymbolAddress((void**)&pFF, g_ffin);
    cudaGetSymbolAddress((void**)&pHID, g_hid);

    const int smem_bytes = GW_WORDS * 4;   // 98,304 B
    static bool attr_set = false;
    if (!attr_set) {
        cudaFuncSetAttribute(gru_mma, cudaFuncAttributeMaxDynamicSharedMemorySize,
                             smem_bytes);
        attr_set = true;
    }

    init_kernel<<<(Bsz * 32 * 16 + 255) / 256, 256>>>();
    wprep_kernel<<<(32 * 32 * 3 * 2 * 32 + 255) / 256, 256>>>(W_hh);

    // GI = x @ W_ih^T + b_ih   (bf16-split mma)
    hgemm<Fsz, H3, true, false, true>
        <<<dim3(BT / 128, H3 / 128), 256>>>(x, W_ih, b_ih, pGI, seq);

    gru_mma<<<128, 256, smem_bytes>>>(pGI, b_hh, seq, pFF);

    // HID = relu(ffin @ W1 + b1)   (bf16-split mma)
    hgemm<Hsz, FFsz, false, true, true>
        <<<dim3(BT / 128, FFsz / 128), 256>>>(pFF, W1, b1, pHID, seq);

    out_gemm_kernel<<<dim3(BT / 128), 256>>>(W2, b2, seq, Y);
}

// round 13
// speedup vs baseline: 1.3900x; 1.3900x over previous
#include <cuda_runtime.h>
#include <cuda_bf16.h>
#include <math.h>

#define Bsz   512
#define Tsz   256
#define Fsz   128
#define Hsz   512
#define FFsz  1024
#define OUTsz 64
#define H3    (3 * Hsz)
#define BT    (Bsz * Tsz)
#define PADV  (-999.0f)
#define BFRAG_WORDS 49152   // per-block_n W slice (tf32): 32kt*3g*2nw*2j*(32lane*4w)

// ---------------- scratch ----------------
__device__ float g_GI[(size_t)BT * H3];
__device__ float g_ffin[(size_t)BT * Hsz];
__device__ float g_hid[(size_t)BT * FFsz];
// fragment-major h (tf32 words, k-mod-4 permuted): [pp][m][kt][16 words]
__device__ unsigned g_hfrag[2][(size_t)Bsz * 32 * 16];
__device__ unsigned g_wfrag[16 * BFRAG_WORDS];
__device__ unsigned g_barg[8 * 32];   // per-m-group barrier counters (128B spaced)

// ---------------- helpers ----------------
__device__ __forceinline__ unsigned long long pack2(float x, float y) {
    unsigned long long r;
    asm("mov.b64 %0,{%1,%2};" : "=l"(r) : "f"(x), "f"(y));
    return r;
}
__device__ __forceinline__ void fma2(unsigned long long& d, unsigned long long a,
                                     unsigned long long b) {
    asm("fma.rn.f32x2 %0,%1,%2,%0;" : "+l"(d) : "l"(a), "l"(b));
}
__device__ __forceinline__ void unpack2(unsigned long long v, float& x, float& y) {
    asm("mov.b64 {%0,%1},%2;" : "=f"(x), "=f"(y) : "l"(v));
}
// bf16 mma m16n8k16 (hgemm path)
__device__ __forceinline__ void mma_bf16(float* d, unsigned a0, unsigned a1,
                                         unsigned a2, unsigned a3,
                                         unsigned b0, unsigned b1) {
    asm volatile(
        "mma.sync.aligned.m16n8k16.row.col.f32.bf16.bf16.f32 "
        "{%0,%1,%2,%3},{%4,%5,%6,%7},{%8,%9},{%0,%1,%2,%3};"
        : "+f"(d[0]), "+f"(d[1]), "+f"(d[2]), "+f"(d[3])
        : "r"(a0), "r"(a1), "r"(a2), "r"(a3), "r"(b0), "r"(b1));
}
// tf32 mma m16n8k8 (GRU path)
__device__ __forceinline__ void mma_tf32(float* d, unsigned a0, unsigned a1,
                                         unsigned a2, unsigned a3,
                                         unsigned b0, unsigned b1) {
    asm volatile(
        "mma.sync.aligned.m16n8k8.row.col.f32.tf32.tf32.f32 "
        "{%0,%1,%2,%3},{%4,%5,%6,%7},{%8,%9},{%0,%1,%2,%3};"
        : "+f"(d[0]), "+f"(d[1]), "+f"(d[2]), "+f"(d[3])
        : "r"(a0), "r"(a1), "r"(a2), "r"(a3), "r"(b0), "r"(b1));
}
__device__ __forceinline__ unsigned bf2pack(float x, float y) {
    __nv_bfloat162 v = __floats2bfloat162_rn(x, y);
    return *(unsigned*)&v;
}
// round-to-nearest tf32 conversion
__device__ __forceinline__ unsigned tf32r(float x) {
    unsigned r;
    asm("cvt.rna.tf32.f32 %0,%1;" : "=r"(r) : "f"(x));
    return r;
}

// ---------------- init ----------------
__global__ void init_kernel() {
    int i = blockIdx.x * blockDim.x + threadIdx.x;
    int tot = Bsz * 32 * 16;
    if (i < tot) g_hfrag[0][i] = 0u;
    if (i < 8 * 32) g_barg[i] = 0u;
}

// ---------------- W_hh -> tf32 fragment layout ----------------
// [bn(16)][kt(32)][g(3)][nw(2)][j(2)][lane(32)][4w]; word q = W[n][kt*16+thr+4q]
__global__ void wprep_kernel(const float* __restrict__ W_hh) {
    int idx = blockIdx.x * blockDim.x + threadIdx.x;
    if (idx >= 16 * 32 * 3 * 2 * 2 * 32) return;
    int lane = idx & 31;
    int r = idx >> 5;
    int j = r & 1;  r >>= 1;
    int nw = r & 1; r >>= 1;
    int g = r % 3;  r /= 3;
    int kt = r & 31;
    int bn = r >> 5;
    int grp = lane >> 2, thr = lane & 3;

    int n_row = g * Hsz + bn * 32 + nw * 16 + j * 8 + grp;
    const float* src = &W_hh[(size_t)n_row * Hsz + kt * 16];
    unsigned* dst = &g_wfrag[(size_t)((((bn * 32 + kt) * 3 + g) * 2 + nw) * 2 + j) * 128 + lane * 4];
#pragma unroll
    for (int q = 0; q < 4; q++) dst[q] = tf32r(src[thr + 4 * q]);
}

// ---------------- plain bf16 MMA GEMM: C = A @ B(^T) + bias, opt relu -----------
// Block tile 128m x 128n, BK=32, 8 warps (2 m-warps x 4 n-warps), 1 mma/product.
template <int KDIM, int NDIM, bool BTRANS, bool RELU, bool SKIP>
__global__ __launch_bounds__(256) void hgemm(const float* __restrict__ A,
                                             const float* __restrict__ Bm,
                                             const float* __restrict__ bias,
                                             float* __restrict__ C,
                                             const int* __restrict__ seq) {
    const int m0 = blockIdx.x * 128;
    const int n0 = blockIdx.y * 128;
    if (SKIP) {
        int b = m0 / Tsz, t0 = m0 % Tsz;
        if (t0 >= seq[b]) return;
    }
    // sA: [q(2)][mt(8)][lane(32)*4w] = 2048 words (8KB)
    // sB: [q(2)][nt(16)][lane(32)*2w] = 2048 words (8KB)
    __shared__ __align__(16) unsigned sA[2048];
    __shared__ __align__(16) unsigned sB[2048];

    const int tid = threadIdx.x;
    const int lane = tid & 31;
    const int wid = tid >> 5;
    const int mw = wid >> 2;       // 0..1
    const int nw = wid & 3;        // 0..3
    const int grp = lane >> 2, thr = lane & 3;

    float acc[4][4][4];
#pragma unroll
    for (int i = 0; i < 4; i++)
#pragma unroll
        for (int j = 0; j < 4; j++)
#pragma unroll
            for (int c = 0; c < 4; c++) acc[i][j][c] = 0.0f;

    for (int k0 = 0; k0 < KDIM; k0 += 32) {
        if (k0 > 0) __syncthreads();
        // ---- fill A fragments: 128 rows x 16 colpairs = 2048 / 256 thr = 8 each
#pragma unroll
        for (int it = 0; it < 8; it++) {
            int fid = tid + it * 256;
            int row = fid >> 4, cp = fid & 15;
            int q = cp >> 3, rem = cp & 7;
            int fthr = rem & 3, whalf = rem >> 2;
            int mt = row >> 4, rin = row & 15;
            int fgrp = rin & 7, wlow = rin >> 3;
            int w = whalf * 2 + wlow;
            int flane = fgrp * 4 + fthr;
            float2 v = *(const float2*)&A[(size_t)(m0 + row) * KDIM + k0 + cp * 2];
            sA[(q * 8 + mt) * 128 + flane * 4 + w] = bf2pack(v.x, v.y);
        }
        // ---- fill B fragments
        if (BTRANS) {
#pragma unroll
            for (int it = 0; it < 8; it++) {
                int fid = tid + it * 256;
                int row = fid >> 4, cp = fid & 15;
                int q = cp >> 3, rem = cp & 7;
                int fthr = rem & 3, w = rem >> 2;
                int nt = row >> 3, fgrp = row & 7;
                int flane = fgrp * 4 + fthr;
                float2 v = *(const float2*)&Bm[(size_t)(n0 + row) * KDIM + k0 + cp * 2];
                sB[(q * 16 + nt) * 64 + flane * 2 + w] = bf2pack(v.x, v.y);
            }
        } else {
#pragma unroll
            for (int it = 0; it < 2; it++) {
                int uid = tid + it * 256;
                int kp = uid >> 5, n4 = uid & 31;
                int n = n4 * 4;
                float4 r0 = *(const float4*)&Bm[(size_t)(k0 + kp * 2) * NDIM + n0 + n];
                float4 r1 = *(const float4*)&Bm[(size_t)(k0 + kp * 2 + 1) * NDIM + n0 + n];
                int q = kp >> 3, p = kp & 7;
                int fthr = p & 3, w = p >> 2;
                float e0[4] = {r0.x, r0.y, r0.z, r0.w};
                float e1[4] = {r1.x, r1.y, r1.z, r1.w};
#pragma unroll
                for (int e = 0; e < 4; e++) {
                    int nn = n + e;
                    int nt = nn >> 3, fgrp = nn & 7;
                    int flane = fgrp * 4 + fthr;
                    sB[(q * 16 + nt) * 64 + flane * 2 + w] = bf2pack(e0[e], e1[e]);
                }
            }
        }
        __syncthreads();

        // ---- compute: 2 k16 slices per chunk, 1 bf16 mma per product
#pragma unroll
        for (int q = 0; q < 2; q++) {
            uint2 bb[4];
#pragma unroll
            for (int j = 0; j < 4; j++)
                bb[j] = *(const uint2*)&sB[(q * 16 + nw * 4 + j) * 64 + lane * 2];
#pragma unroll
            for (int i = 0; i < 4; i++) {
                uint4 ah = *(const uint4*)&sA[(q * 8 + mw * 4 + i) * 128 + lane * 4];
#pragma unroll
                for (int j = 0; j < 4; j++)
                    mma_bf16(acc[i][j], ah.x, ah.y, ah.z, ah.w, bb[j].x, bb[j].y);
            }
        }
    }

    // ---- epilogue
#pragma unroll
    for (int i = 0; i < 4; i++) {
        const int r0 = m0 + (mw * 4 + i) * 16 + grp;
#pragma unroll
        for (int j = 0; j < 4; j++) {
            const int col = n0 + (nw * 4 + j) * 8 + thr * 2;
            const float b0 = bias[col], b1 = bias[col + 1];
            float o0 = acc[i][j][0] + b0, o1 = acc[i][j][1] + b1;
            float o2 = acc[i][j][2] + b0, o3 = acc[i][j][3] + b1;
            if (RELU) {
                o0 = fmaxf(o0, 0.f); o1 = fmaxf(o1, 0.f);
                o2 = fmaxf(o2, 0.f); o3 = fmaxf(o3, 0.f);
            }
            *(float2*)&C[(size_t)r0 * NDIM + col] = make_float2(o0, o1);
            *(float2*)&C[(size_t)(r0 + 8) * NDIM + col] = make_float2(o2, o3);
        }
    }
}

// ---------------- persistent tf32 tensor-core GRU (R11 version; verified) -------
__global__ __launch_bounds__(256, 1) void gru_mma(
    const float* __restrict__ GI, const float* __restrict__ b_hh,
    const int* __restrict__ seq, float* __restrict__ ffin) {
    extern __shared__ unsigned Bw[];   // [kt][g][nw][j][lane*4] = 192KB

    const int tid = threadIdx.x;
    const int lane = tid & 31;
    const int wid  = tid >> 5;
    const int mw = wid & 3, nw = wid >> 2;
    const int grp = lane >> 2, thr = lane & 3;
    const int mgrp = blockIdx.x >> 4;
    const int m0 = mgrp * 64;
    const int block_n = blockIdx.x & 15;
    const int hb = block_n * 32;
    const int kt_g = block_n * 2 + nw;

    {
        const uint4* src = (const uint4*)&g_wfrag[(size_t)block_n * BFRAG_WORDS];
        uint4* dst = (uint4*)Bw;
        for (int i = tid; i < BFRAG_WORDS / 4; i += 256) dst[i] = src[i];
    }

    const int m_a = m0 + mw * 16 + grp;
    const int m_b = m_a + 8;
    const int seq_a = seq[m_a];
    const int seq_b = seq[m_b];

    float2 bh[2][3];
#pragma unroll
    for (int j = 0; j < 2; j++) {
        const int hcol = hb + nw * 16 + j * 8 + thr * 2;
#pragma unroll
        for (int g = 0; g < 3; g++) bh[j][g] = *(const float2*)&b_hh[g * Hsz + hcol];
    }

    const int w_j0 = (thr & 1) * 8 + (thr >> 1);
    const int w_j1 = w_j0 + 2;

    float hreg[2][2][2];
#pragma unroll
    for (int a = 0; a < 2; a++)
#pragma unroll
        for (int b = 0; b < 2; b++) { hreg[a][b][0] = 0.0f; hreg[a][b][1] = 0.0f; }

    __syncthreads();

    for (int t = 0; t < Tsz; ++t) {
        const int pp = t & 1;
        const unsigned* __restrict__ Af = g_hfrag[pp];
        unsigned* __restrict__ Ao = g_hfrag[pp ^ 1];

        float2 pgi[2][2][3];
#pragma unroll
        for (int half = 0; half < 2; half++) {
            const size_t gib = ((size_t)(half ? m_b : m_a) * Tsz + t) * (size_t)H3;
#pragma unroll
            for (int j = 0; j < 2; j++) {
                const int hcol = hb + nw * 16 + j * 8 + thr * 2;
#pragma unroll
                for (int g = 0; g < 3; g++)
                    pgi[half][j][g] = *(const float2*)&GI[gib + g * Hsz + hcol];
            }
        }

        float acc[2][3][4];
#pragma unroll
        for (int j = 0; j < 2; j++)
#pragma unroll
            for (int g = 0; g < 3; g++)
#pragma unroll
                for (int c = 0; c < 4; c++) acc[j][g][c] = 0.0f;

        uint4 pfA[2][2];
        const size_t abase_a = (size_t)m_a * 32;
        const size_t abase_b = (size_t)m_b * 32;
#pragma unroll
        for (int p = 0; p < 2; p++) {
            pfA[p][0] = __ldcg((const uint4*)&Af[(abase_a + p) * 16 + thr * 4]);
            pfA[p][1] = __ldcg((const uint4*)&Af[(abase_b + p) * 16 + thr * 4]);
        }

#pragma unroll 4
        for (int kt = 0; kt < 32; ++kt) {
            const uint4 ara = pfA[kt & 1][0];
            const uint4 arb = pfA[kt & 1][1];
            if (kt < 30) {
                pfA[kt & 1][0] = __ldcg((const uint4*)&Af[(abase_a + kt + 2) * 16 + thr * 4]);
                pfA[kt & 1][1] = __ldcg((const uint4*)&Af[(abase_b + kt + 2) * 16 + thr * 4]);
            }
#pragma unroll
            for (int g = 0; g < 3; g++) {
                const int base = (((kt * 3 + g) * 2 + nw) * 2) * 128 + lane * 4;
                uint4 b0 = *(const uint4*)&Bw[base];
                uint4 b1 = *(const uint4*)&Bw[base + 128];
                mma_tf32(acc[0][g], ara.x, arb.x, ara.y, arb.y, b0.x, b0.y);
                mma_tf32(acc[0][g], ara.z, arb.z, ara.w, arb.w, b0.z, b0.w);
                mma_tf32(acc[1][g], ara.x, arb.x, ara.y, arb.y, b1.x, b1.y);
                mma_tf32(acc[1][g], ara.z, arb.z, ara.w, arb.w, b1.z, b1.w);
            }
        }

#pragma unroll
        for (int half = 0; half < 2; half++) {
            const int m = half ? m_b : m_a;
            const int sl = half ? seq_b : seq_a;
            const int ai = half * 2;
            const size_t bt = (size_t)m * Tsz + t;
#pragma unroll
            for (int j = 0; j < 2; j++) {
                const int hcol = hb + nw * 16 + j * 8 + thr * 2;
                if (t < sl) {
                    const float ghr0 = acc[j][0][ai] + bh[j][0].x;
                    const float ghr1 = acc[j][0][ai + 1] + bh[j][0].y;
                    const float ghz0 = acc[j][1][ai] + bh[j][1].x;
                    const float ghz1 = acc[j][1][ai + 1] + bh[j][1].y;
                    const float ghn0 = acc[j][2][ai] + bh[j][2].x;
                    const float ghn1 = acc[j][2][ai + 1] + bh[j][2].y;
                    const float r0 = __fdividef(1.0f, 1.0f + __expf(-(pgi[half][j][0].x + ghr0)));
                    const float r1 = __fdividef(1.0f, 1.0f + __expf(-(pgi[half][j][0].y + ghr1)));
                    const float z0 = __fdividef(1.0f, 1.0f + __expf(-(pgi[half][j][1].x + ghz0)));
                    const float z1 = __fdividef(1.0f, 1.0f + __expf(-(pgi[half][j][1].y + ghz1)));
                    const float n0v = tanhf(pgi[half][j][2].x + r0 * ghn0);
                    const float n1v = tanhf(pgi[half][j][2].y + r1 * ghn1);
                    const float hn0 = (1.0f - z0) * n0v + z0 * hreg[half][j][0];
                    const float hn1 = (1.0f - z1) * n1v + z1 * hreg[half][j][1];
                    hreg[half][j][0] = hn0;
                    hreg[half][j][1] = hn1;
                    *(float2*)&ffin[bt * (size_t)Hsz + hcol] = make_float2(hn0, hn1);
                } else {
                    *(float2*)&ffin[bt * (size_t)Hsz + hcol] = make_float2(0.0f, 0.0f);
                }
            }
            const size_t ab = ((size_t)m * 32 + kt_g) * 16;
            Ao[ab + w_j0]     = tf32r(hreg[half][0][0]);
            Ao[ab + w_j0 + 4] = tf32r(hreg[half][0][1]);
            Ao[ab + w_j1]     = tf32r(hreg[half][1][0]);
            Ao[ab + w_j1 + 4] = tf32r(hreg[half][1][1]);
        }

        if (t < Tsz - 1) {
            __threadfence();
            __syncthreads();
            if (tid == 0) {
                unsigned* ctr = &g_barg[mgrp * 32];
                atomicAdd(ctr, 1u);
                const unsigned target = 16u * (unsigned)(t + 1);
                while (atomicAdd(ctr, 0u) < target) __nanosleep(32);
            }
            __syncthreads();
        }
    }
}

// ---------------- output GEMM: Y = hid @ W2 + b2, PAD-masked ---------------------
__global__ __launch_bounds__(256) void out_gemm_kernel(const float* __restrict__ W2,
                                                       const float* __restrict__ b2,
                                                       const int* __restrict__ seq,
                                                       float* __restrict__ Y) {
    const int m0 = blockIdx.x * 128;
    const int b  = m0 / Tsz;
    const int t0 = m0 % Tsz;
    const int tid = threadIdx.x;
    const int slen = seq[b];
    if (t0 >= slen) {
        float4 pv = make_float4(PADV, PADV, PADV, PADV);
#pragma unroll
        for (int l = 0; l < 8; l++) {
            int idx = tid + l * 256;
            *(float4*)&Y[(size_t)(m0 + (idx >> 4)) * OUTsz + (idx & 15) * 4] = pv;
        }
        return;
    }
    __shared__ float As[32][128];
    __shared__ float Bs[32][64];
    const int tx = tid % 16, ty = tid / 16;
    const int row0 = ty * 8, col0 = tx * 4;
    unsigned long long acc[8][2];
#pragma unroll
    for (int i = 0; i < 8; i++) { acc[i][0] = 0ULL; acc[i][1] = 0ULL; }

    for (int k0 = 0; k0 < FFsz; k0 += 32) {
#pragma unroll
        for (int l = 0; l < 4; l++) {
            int idx = tid + l * 256;
            int r = idx >> 3, c4 = (idx & 7) * 4;
            float4 v = *(const float4*)&g_hid[(size_t)(m0 + r) * FFsz + k0 + c4];
            As[c4 + 0][r] = v.x; As[c4 + 1][r] = v.y;
            As[c4 + 2][r] = v.z; As[c4 + 3][r] = v.w;
        }
#pragma unroll
        for (int l = 0; l < 2; l++) {
            int idx = tid + l * 256;
            int k = idx >> 4, c4 = (idx & 15) * 4;
            *(float4*)&Bs[k][c4] = *(const float4*)&W2[(size_t)(k0 + k) * OUTsz + c4];
        }
        __syncthreads();
#pragma unroll
        for (int k = 0; k < 32; k++) {
            float4 a0 = *(const float4*)&As[k][row0];
            float4 a1 = *(const float4*)&As[k][row0 + 4];
            unsigned long long b0 = *(const unsigned long long*)&Bs[k][col0];
            unsigned long long b1 = *(const unsigned long long*)&Bs[k][col0 + 2];
            float av[8] = {a0.x, a0.y, a0.z, a0.w, a1.x, a1.y, a1.z, a1.w};
#pragma unroll
            for (int i = 0; i < 8; i++) {
                unsigned long long ad = pack2(av[i], av[i]);
                fma2(acc[i][0], ad, b0);
                fma2(acc[i][1], ad, b1);
            }
        }
        __syncthreads();
    }
#pragma unroll
    for (int i = 0; i < 8; i++) {
        int m = m0 + row0 + i;
        int t = t0 + row0 + i;
        float o[4];
        unpack2(acc[i][0], o[0], o[1]);
        unpack2(acc[i][1], o[2], o[3]);
        float4 v;
        if (t < slen) {
            v = make_float4(o[0] + b2[col0 + 0], o[1] + b2[col0 + 1],
                            o[2] + b2[col0 + 2], o[3] + b2[col0 + 3]);
        } else {
            v = make_float4(PADV, PADV, PADV, PADV);
        }
        *(float4*)&Y[(size_t)m * OUTsz + col0] = v;
    }
}

// ---------------- launch ----------------
extern "C" void kernel_launch(void* const* d_in, const int* in_sizes, int n_in,
                              void* d_out, int out_size) {
    (void)in_sizes; (void)n_in; (void)out_size;
    const float* x    = (const float*)d_in[0];
    const int*   seq  = (const int*)d_in[1];
    const float* W_ih = (const float*)d_in[2];
    const float* W_hh = (const float*)d_in[3];
    const float* b_ih = (const float*)d_in[4];
    const float* b_hh = (const float*)d_in[5];
    const float* W1   = (const float*)d_in[6];
    const float* b1   = (const float*)d_in[7];
    const float* W2   = (const float*)d_in[8];
    const float* b2   = (const float*)d_in[9];
    float* Y = (float*)d_out;

    float *pGI = nullptr, *pFF = nullptr, *pHID = nullptr;
    cudaGetSymbolAddress((void**)&pGI, g_GI);
    cudaGetSymbolAddress((void**)&pFF, g_ffin);
    cudaGetSymbolAddress((void**)&pHID, g_hid);

    const int smem_bytes = BFRAG_WORDS * 4;   // 196,608 B
    static bool attr_set = false;
    if (!attr_set) {
        cudaFuncSetAttribute(gru_mma, cudaFuncAttributeMaxDynamicSharedMemorySize,
                             smem_bytes);
        attr_set = true;
    }

    init_kernel<<<(Bsz * 32 * 16 + 255) / 256, 256>>>();
    wprep_kernel<<<(16 * 32 * 3 * 2 * 2 * 32 + 255) / 256, 256>>>(W_hh);

    // GI = x @ W_ih^T + b_ih   (plain bf16 mma)
    hgemm<Fsz, H3, true, false, true>
        <<<dim3(BT / 128, H3 / 128), 256>>>(x, W_ih, b_ih, pGI, seq);

    gru_mma<<<128, 256, smem_bytes>>>(pGI, b_hh, seq, pFF);

    // HID = relu(ffin @ W1 + b1)   (plain bf16 mma)
    hgemm<Hsz, FFsz, false, true, true>
        <<<dim3(BT / 128, FFsz / 128), 256>>>(pFF, W1, b1, pHID, seq);

    out_gemm_kernel<<<dim3(BT / 128), 256>>>(W2, b2, seq, Y);
}

// round 14
// speedup vs baseline: 1.6935x; 1.2184x over previous
#include <cuda_runtime.h>
#include <cuda_bf16.h>
#include <math.h>

#define Bsz   512
#define Tsz   256
#define Fsz   128
#define Hsz   512
#define FFsz  1024
#define OUTsz 64
#define H3    (3 * Hsz)
#define BT    (Bsz * Tsz)
#define PADV  (-999.0f)
#define GW_WORDS 24576   // per-block_n W slice (bf16): 32kt*3g*2nw*(32lane*4w) = 96KB

// ---------------- scratch ----------------
__device__ float g_GI[(size_t)BT * H3];
__device__ float g_ffin[(size_t)BT * Hsz];
__device__ float g_hid[(size_t)BT * FFsz];
// fragment-major h (bf16x2 words, kp-paired): [pp][m][kp(16)][16 words]
__device__ unsigned g_hfrag[2][(size_t)Bsz * 256];
__device__ unsigned g_wfrag[16 * GW_WORDS];
__device__ unsigned g_barg[8 * 32];   // per-m-group barrier counters (128B spaced)

// ---------------- helpers ----------------
__device__ __forceinline__ unsigned long long pack2(float x, float y) {
    unsigned long long r;
    asm("mov.b64 %0,{%1,%2};" : "=l"(r) : "f"(x), "f"(y));
    return r;
}
__device__ __forceinline__ void fma2(unsigned long long& d, unsigned long long a,
                                     unsigned long long b) {
    asm("fma.rn.f32x2 %0,%1,%2,%0;" : "+l"(d) : "l"(a), "l"(b));
}
__device__ __forceinline__ void unpack2(unsigned long long v, float& x, float& y) {
    asm("mov.b64 {%0,%1},%2;" : "=f"(x), "=f"(y) : "l"(v));
}
__device__ __forceinline__ void mma_bf16(float* d, unsigned a0, unsigned a1,
                                         unsigned a2, unsigned a3,
                                         unsigned b0, unsigned b1) {
    asm volatile(
        "mma.sync.aligned.m16n8k16.row.col.f32.bf16.bf16.f32 "
        "{%0,%1,%2,%3},{%4,%5,%6,%7},{%8,%9},{%0,%1,%2,%3};"
        : "+f"(d[0]), "+f"(d[1]), "+f"(d[2]), "+f"(d[3])
        : "r"(a0), "r"(a1), "r"(a2), "r"(a3), "r"(b0), "r"(b1));
}
__device__ __forceinline__ unsigned bf2pack(float x, float y) {
    __nv_bfloat162 v = __floats2bfloat162_rn(x, y);
    return *(unsigned*)&v;
}

// ---------------- init ----------------
__global__ void init_kernel() {
    int i = blockIdx.x * blockDim.x + threadIdx.x;
    int tot = Bsz * 256;
    if (i < tot) g_hfrag[0][i] = 0u;
    if (i < 8 * 32) g_barg[i] = 0u;
}

// ---------------- W_hh -> bf16 fragment layout ----------------
// [bn(16)][kt(32)][g(3)][nw(2)][lane(32)][4w: j0b0,j0b1,j1b0,j1b1]
__global__ void wprep_kernel(const float* __restrict__ W_hh) {
    int idx = blockIdx.x * blockDim.x + threadIdx.x;
    if (idx >= 16 * 32 * 3 * 2 * 32) return;
    int lane = idx & 31;
    int r = idx >> 5;
    int nw = r & 1; r >>= 1;
    int g = r % 3;  r /= 3;
    int kt = r & 31;
    int bn = r >> 5;
    int grp = lane >> 2, thr = lane & 3;

    unsigned w[4];
#pragma unroll
    for (int j = 0; j < 2; j++) {
        int n_row = g * Hsz + bn * 32 + nw * 16 + j * 8 + grp;
        const float* src = &W_hh[(size_t)n_row * Hsz + kt * 16 + thr * 2];
        w[j * 2 + 0] = bf2pack(src[0], src[1]);
        w[j * 2 + 1] = bf2pack(src[8], src[9]);
    }
    unsigned* dst = &g_wfrag[(size_t)(((bn * 32 + kt) * 3 + g) * 2 + nw) * 128 + lane * 4];
#pragma unroll
    for (int i = 0; i < 4; i++) dst[i] = w[i];
}

// ---------------- plain bf16 MMA GEMM (R13 version; verified) -------------------
template <int KDIM, int NDIM, bool BTRANS, bool RELU, bool SKIP>
__global__ __launch_bounds__(256) void hgemm(const float* __restrict__ A,
                                             const float* __restrict__ Bm,
                                             const float* __restrict__ bias,
                                             float* __restrict__ C,
                                             const int* __restrict__ seq) {
    const int m0 = blockIdx.x * 128;
    const int n0 = blockIdx.y * 128;
    if (SKIP) {
        int b = m0 / Tsz, t0 = m0 % Tsz;
        if (t0 >= seq[b]) return;
    }
    __shared__ __align__(16) unsigned sA[2048];
    __shared__ __align__(16) unsigned sB[2048];

    const int tid = threadIdx.x;
    const int lane = tid & 31;
    const int wid = tid >> 5;
    const int mw = wid >> 2;
    const int nw = wid & 3;
    const int grp = lane >> 2, thr = lane & 3;

    float acc[4][4][4];
#pragma unroll
    for (int i = 0; i < 4; i++)
#pragma unroll
        for (int j = 0; j < 4; j++)
#pragma unroll
            for (int c = 0; c < 4; c++) acc[i][j][c] = 0.0f;

    for (int k0 = 0; k0 < KDIM; k0 += 32) {
        if (k0 > 0) __syncthreads();
#pragma unroll
        for (int it = 0; it < 8; it++) {
            int fid = tid + it * 256;
            int row = fid >> 4, cp = fid & 15;
            int q = cp >> 3, rem = cp & 7;
            int fthr = rem & 3, whalf = rem >> 2;
            int mt = row >> 4, rin = row & 15;
            int fgrp = rin & 7, wlow = rin >> 3;
            int w = whalf * 2 + wlow;
            int flane = fgrp * 4 + fthr;
            float2 v = *(const float2*)&A[(size_t)(m0 + row) * KDIM + k0 + cp * 2];
            sA[(q * 8 + mt) * 128 + flane * 4 + w] = bf2pack(v.x, v.y);
        }
        if (BTRANS) {
#pragma unroll
            for (int it = 0; it < 8; it++) {
                int fid = tid + it * 256;
                int row = fid >> 4, cp = fid & 15;
                int q = cp >> 3, rem = cp & 7;
                int fthr = rem & 3, w = rem >> 2;
                int nt = row >> 3, fgrp = row & 7;
                int flane = fgrp * 4 + fthr;
                float2 v = *(const float2*)&Bm[(size_t)(n0 + row) * KDIM + k0 + cp * 2];
                sB[(q * 16 + nt) * 64 + flane * 2 + w] = bf2pack(v.x, v.y);
            }
        } else {
#pragma unroll
            for (int it = 0; it < 2; it++) {
                int uid = tid + it * 256;
                int kp = uid >> 5, n4 = uid & 31;
                int n = n4 * 4;
                float4 r0 = *(const float4*)&Bm[(size_t)(k0 + kp * 2) * NDIM + n0 + n];
                float4 r1 = *(const float4*)&Bm[(size_t)(k0 + kp * 2 + 1) * NDIM + n0 + n];
                int q = kp >> 3, p = kp & 7;
                int fthr = p & 3, w = p >> 2;
                float e0[4] = {r0.x, r0.y, r0.z, r0.w};
                float e1[4] = {r1.x, r1.y, r1.z, r1.w};
#pragma unroll
                for (int e = 0; e < 4; e++) {
                    int nn = n + e;
                    int nt = nn >> 3, fgrp = nn & 7;
                    int flane = fgrp * 4 + fthr;
                    sB[(q * 16 + nt) * 64 + flane * 2 + w] = bf2pack(e0[e], e1[e]);
                }
            }
        }
        __syncthreads();

#pragma unroll
        for (int q = 0; q < 2; q++) {
            uint2 bb[4];
#pragma unroll
            for (int j = 0; j < 4; j++)
                bb[j] = *(const uint2*)&sB[(q * 16 + nw * 4 + j) * 64 + lane * 2];
#pragma unroll
            for (int i = 0; i < 4; i++) {
                uint4 ah = *(const uint4*)&sA[(q * 8 + mw * 4 + i) * 128 + lane * 4];
#pragma unroll
                for (int j = 0; j < 4; j++)
                    mma_bf16(acc[i][j], ah.x, ah.y, ah.z, ah.w, bb[j].x, bb[j].y);
            }
        }
    }

#pragma unroll
    for (int i = 0; i < 4; i++) {
        const int r0 = m0 + (mw * 4 + i) * 16 + grp;
#pragma unroll
        for (int j = 0; j < 4; j++) {
            const int col = n0 + (nw * 4 + j) * 8 + thr * 2;
            const float b0 = bias[col], b1 = bias[col + 1];
            float o0 = acc[i][j][0] + b0, o1 = acc[i][j][1] + b1;
            float o2 = acc[i][j][2] + b0, o3 = acc[i][j][3] + b1;
            if (RELU) {
                o0 = fmaxf(o0, 0.f); o1 = fmaxf(o1, 0.f);
                o2 = fmaxf(o2, 0.f); o3 = fmaxf(o3, 0.f);
            }
            *(float2*)&C[(size_t)r0 * NDIM + col] = make_float2(o0, o1);
            *(float2*)&C[(size_t)(r0 + 8) * NDIM + col] = make_float2(o2, o3);
        }
    }
}

// ---------------- persistent bf16 tensor-core GRU -------------------------------
// Grid=128. Block: 64 batch x 32 hidden (x3 gates). 96KB W smem. Per kt per warp:
// 6 mma, 3 LDS.128; one LDG.128 per row per kp (2 kts). h fp32 in registers.
__global__ __launch_bounds__(256, 1) void gru_mma(
    const float* __restrict__ GI, const float* __restrict__ b_hh,
    const int* __restrict__ seq, float* __restrict__ ffin) {
    extern __shared__ unsigned Bw[];   // [kt][g][nw][lane*4] = 96KB

    const int tid = threadIdx.x;
    const int lane = tid & 31;
    const int wid  = tid >> 5;
    const int mw = wid & 3, nw = wid >> 2;
    const int grp = lane >> 2, thr = lane & 3;
    const int mgrp = blockIdx.x >> 4;
    const int m0 = mgrp * 64;
    const int block_n = blockIdx.x & 15;
    const int hb = block_n * 32;
    const int kt_g = block_n * 2 + nw;
    const int kp_g = kt_g >> 1, par_g = kt_g & 1;

    // load 96KB W slice into persistent smem
    {
        const uint4* src = (const uint4*)&g_wfrag[(size_t)block_n * GW_WORDS];
        uint4* dst = (uint4*)Bw;
        for (int i = tid; i < GW_WORDS / 4; i += 256) dst[i] = src[i];
    }

    const int m_a = m0 + mw * 16 + grp;
    const int m_b = m_a + 8;
    const int seq_a = seq[m_a];
    const int seq_b = seq[m_b];

    float2 bh[2][3];
#pragma unroll
    for (int j = 0; j < 2; j++) {
        const int hcol = hb + nw * 16 + j * 8 + thr * 2;
#pragma unroll
        for (int g = 0; g < 3; g++) bh[j][g] = *(const float2*)&b_hh[g * Hsz + hcol];
    }

    float hreg[2][2][2];   // [half][j][pair]
#pragma unroll
    for (int a = 0; a < 2; a++)
#pragma unroll
        for (int b = 0; b < 2; b++) { hreg[a][b][0] = 0.0f; hreg[a][b][1] = 0.0f; }

    __syncthreads();

    for (int t = 0; t < Tsz; ++t) {
        const int pp = t & 1;
        const unsigned* __restrict__ Af = g_hfrag[pp];
        unsigned* __restrict__ Ao = g_hfrag[pp ^ 1];

        // prefetch GI
        float2 pgi[2][2][3];
#pragma unroll
        for (int half = 0; half < 2; half++) {
            const size_t gib = ((size_t)(half ? m_b : m_a) * Tsz + t) * (size_t)H3;
#pragma unroll
            for (int j = 0; j < 2; j++) {
                const int hcol = hb + nw * 16 + j * 8 + thr * 2;
#pragma unroll
                for (int g = 0; g < 3; g++)
                    pgi[half][j][g] = *(const float2*)&GI[gib + g * Hsz + hcol];
            }
        }

        float acc[2][3][4];   // [j][g][c]
#pragma unroll
        for (int j = 0; j < 2; j++)
#pragma unroll
            for (int g = 0; g < 3; g++)
#pragma unroll
                for (int c = 0; c < 4; c++) acc[j][g][c] = 0.0f;

        // distance-2 A prefetch (per kp: one uint4 per row = 2 kt groups)
        uint4 pfA[2][2];
        const size_t abase_a = (size_t)m_a * 16;
        const size_t abase_b = (size_t)m_b * 16;
#pragma unroll
        for (int p = 0; p < 2; p++) {
            pfA[p][0] = __ldcg((const uint4*)&Af[(abase_a + p) * 16 + thr * 4]);
            pfA[p][1] = __ldcg((const uint4*)&Af[(abase_b + p) * 16 + thr * 4]);
        }

#pragma unroll 4
        for (int kp = 0; kp < 16; ++kp) {
            const uint4 arA = pfA[kp & 1][0];  // [kt0b0, kt0b1, kt1b0, kt1b1] m_a
            const uint4 arB = pfA[kp & 1][1];  // same for m_b
            if (kp < 14) {
                pfA[kp & 1][0] = __ldcg((const uint4*)&Af[(abase_a + kp + 2) * 16 + thr * 4]);
                pfA[kp & 1][1] = __ldcg((const uint4*)&Af[(abase_b + kp + 2) * 16 + thr * 4]);
            }
            // kt even
#pragma unroll
            for (int g = 0; g < 3; g++) {
                const uint4 bb = *(const uint4*)&Bw[(size_t)(((kp * 2) * 3 + g) * 2 + nw) * 128 + lane * 4];
                mma_bf16(acc[0][g], arA.x, arB.x, arA.y, arB.y, bb.x, bb.y);
                mma_bf16(acc[1][g], arA.x, arB.x, arA.y, arB.y, bb.z, bb.w);
            }
            // kt odd
#pragma unroll
            for (int g = 0; g < 3; g++) {
                const uint4 bb = *(const uint4*)&Bw[(size_t)(((kp * 2 + 1) * 3 + g) * 2 + nw) * 128 + lane * 4];
                mma_bf16(acc[0][g], arA.z, arB.z, arA.w, arB.w, bb.x, bb.y);
                mma_bf16(acc[1][g], arA.z, arB.z, arA.w, arB.w, bb.z, bb.w);
            }
        }

        // epilogue: gates + state update (h fp32 in registers)
#pragma unroll
        for (int half = 0; half < 2; half++) {
            const int m = half ? m_b : m_a;
            const int sl = half ? seq_b : seq_a;
            const int ai = half * 2;
            const size_t bt = (size_t)m * Tsz + t;
#pragma unroll
            for (int j = 0; j < 2; j++) {
                const int hcol = hb + nw * 16 + j * 8 + thr * 2;
                if (t < sl) {
                    const float ghr0 = acc[j][0][ai] + bh[j][0].x;
                    const float ghr1 = acc[j][0][ai + 1] + bh[j][0].y;
                    const float ghz0 = acc[j][1][ai] + bh[j][1].x;
                    const float ghz1 = acc[j][1][ai + 1] + bh[j][1].y;
                    const float ghn0 = acc[j][2][ai] + bh[j][2].x;
                    const float ghn1 = acc[j][2][ai + 1] + bh[j][2].y;
                    const float r0 = __fdividef(1.0f, 1.0f + __expf(-(pgi[half][j][0].x + ghr0)));
                    const float r1 = __fdividef(1.0f, 1.0f + __expf(-(pgi[half][j][0].y + ghr1)));
                    const float z0 = __fdividef(1.0f, 1.0f + __expf(-(pgi[half][j][1].x + ghz0)));
                    const float z1 = __fdividef(1.0f, 1.0f + __expf(-(pgi[half][j][1].y + ghz1)));
                    const float n0v = tanhf(pgi[half][j][2].x + r0 * ghn0);
                    const float n1v = tanhf(pgi[half][j][2].y + r1 * ghn1);
                    const float hn0 = (1.0f - z0) * n0v + z0 * hreg[half][j][0];
                    const float hn1 = (1.0f - z1) * n1v + z1 * hreg[half][j][1];
                    hreg[half][j][0] = hn0;
                    hreg[half][j][1] = hn1;
                    *(float2*)&ffin[bt * (size_t)Hsz + hcol] = make_float2(hn0, hn1);
                } else {
                    *(float2*)&ffin[bt * (size_t)Hsz + hcol] = make_float2(0.0f, 0.0f);
                }
            }
            // one uint2 store: [j0 pack, j1 pack] at kp_g / parity slot
            const size_t ab = ((size_t)m * 16 + kp_g) * 16 + thr * 4 + par_g * 2;
            uint2 st;
            st.x = bf2pack(hreg[half][0][0], hreg[half][0][1]);
            st.y = bf2pack(hreg[half][1][0], hreg[half][1][1]);
            *(uint2*)&Ao[ab] = st;
        }

        // per-m-group barrier (16 blocks)
        if (t < Tsz - 1) {
            __threadfence();
            __syncthreads();
            if (tid == 0) {
                unsigned* ctr = &g_barg[mgrp * 32];
                atomicAdd(ctr, 1u);
                const unsigned target = 16u * (unsigned)(t + 1);
                while (atomicAdd(ctr, 0u) < target) __nanosleep(32);
            }
            __syncthreads();
        }
    }
}

// ---------------- output GEMM: Y = hid @ W2 + b2, PAD-masked ---------------------
__global__ __launch_bounds__(256) void out_gemm_kernel(const float* __restrict__ W2,
                                                       const float* __restrict__ b2,
                                                       const int* __restrict__ seq,
                                                       float* __restrict__ Y) {
    const int m0 = blockIdx.x * 128;
    const int b  = m0 / Tsz;
    const int t0 = m0 % Tsz;
    const int tid = threadIdx.x;
    const int slen = seq[b];
    if (t0 >= slen) {
        float4 pv = make_float4(PADV, PADV, PADV, PADV);
#pragma unroll
        for (int l = 0; l < 8; l++) {
            int idx = tid + l * 256;
            *(float4*)&Y[(size_t)(m0 + (idx >> 4)) * OUTsz + (idx & 15) * 4] = pv;
        }
        return;
    }
    __shared__ float As[32][128];
    __shared__ float Bs[32][64];
    const int tx = tid % 16, ty = tid / 16;
    const int row0 = ty * 8, col0 = tx * 4;
    unsigned long long acc[8][2];
#pragma unroll
    for (int i = 0; i < 8; i++) { acc[i][0] = 0ULL; acc[i][1] = 0ULL; }

    for (int k0 = 0; k0 < FFsz; k0 += 32) {
#pragma unroll
        for (int l = 0; l < 4; l++) {
            int idx = tid + l * 256;
            int r = idx >> 3, c4 = (idx & 7) * 4;
            float4 v = *(const float4*)&g_hid[(size_t)(m0 + r) * FFsz + k0 + c4];
            As[c4 + 0][r] = v.x; As[c4 + 1][r] = v.y;
            As[c4 + 2][r] = v.z; As[c4 + 3][r] = v.w;
        }
#pragma unroll
        for (int l = 0; l < 2; l++) {
            int idx = tid + l * 256;
            int k = idx >> 4, c4 = (idx & 15) * 4;
            *(float4*)&Bs[k][c4] = *(const float4*)&W2[(size_t)(k0 + k) * OUTsz + c4];
        }
        __syncthreads();
#pragma unroll
        for (int k = 0; k < 32; k++) {
            float4 a0 = *(const float4*)&As[k][row0];
            float4 a1 = *(const float4*)&As[k][row0 + 4];
            unsigned long long b0 = *(const unsigned long long*)&Bs[k][col0];
            unsigned long long b1 = *(const unsigned long long*)&Bs[k][col0 + 2];
            float av[8] = {a0.x, a0.y, a0.z, a0.w, a1.x, a1.y, a1.z, a1.w};
#pragma unroll
            for (int i = 0; i < 8; i++) {
                unsigned long long ad = pack2(av[i], av[i]);
                fma2(acc[i][0], ad, b0);
                fma2(acc[i][1], ad, b1);
            }
        }
        __syncthreads();
    }
#pragma unroll
    for (int i = 0; i < 8; i++) {
        int m = m0 + row0 + i;
        int t = t0 + row0 + i;
        float o[4];
        unpack2(acc[i][0], o[0], o[1]);
        unpack2(acc[i][1], o[2], o[3]);
        float4 v;
        if (t < slen) {
            v = make_float4(o[0] + b2[col0 + 0], o[1] + b2[col0 + 1],
                            o[2] + b2[col0 + 2], o[3] + b2[col0 + 3]);
        } else {
            v = make_float4(PADV, PADV, PADV, PADV);
        }
        *(float4*)&Y[(size_t)m * OUTsz + col0] = v;
    }
}

// ---------------- launch ----------------
extern "C" void kernel_launch(void* const* d_in, const int* in_sizes, int n_in,
                              void* d_out, int out_size) {
    (void)in_sizes; (void)n_in; (void)out_size;
    const float* x    = (const float*)d_in[0];
    const int*   seq  = (const int*)d_in[1];
    const float* W_ih = (const float*)d_in[2];
    const float* W_hh = (const float*)d_in[3];
    const float* b_ih = (const float*)d_in[4];
    const float* b_hh = (const float*)d_in[5];
    const float* W1   = (const float*)d_in[6];
    const float* b1   = (const float*)d_in[7];
    const float* W2   = (const float*)d_in[8];
    const float* b2   = (const float*)d_in[9];
    float* Y = (float*)d_out;

    float *pGI = nullptr, *pFF = nullptr, *pHID = nullptr;
    cudaGetSymbolAddress((void**)&pGI, g_GI);
    cudaGetSymbolAddress((void**)&pFF, g_ffin);
    cudaGetSymbolAddress((void**)&pHID, g_hid);

    const int smem_bytes = GW_WORDS * 4;   // 98,304 B
    static bool attr_set = false;
    if (!attr_set) {
        cudaFuncSetAttribute(gru_mma, cudaFuncAttributeMaxDynamicSharedMemorySize,
                             smem_bytes);
        attr_set = true;
    }

    init_kernel<<<(Bsz * 256 + 255) / 256, 256>>>();
    wprep_kernel<<<(16 * 32 * 3 * 2 * 32 + 255) / 256, 256>>>(W_hh);

    // GI = x @ W_ih^T + b_ih   (plain bf16 mma)
    hgemm<Fsz, H3, true, false, true>
        <<<dim3(BT / 128, H3 / 128), 256>>>(x, W_ih, b_ih, pGI, seq);

    gru_mma<<<128, 256, smem_bytes>>>(pGI, b_hh, seq, pFF);

    // HID = relu(ffin @ W1 + b1)   (plain bf16 mma)
    hgemm<Hsz, FFsz, false, true, true>
        <<<dim3(BT / 128, FFsz / 128), 256>>>(pFF, W1, b1, pHID, seq);

    out_gemm_kernel<<<dim3(BT / 128), 256>>>(W2, b2, seq, Y);
}

// round 15
// speedup vs baseline: 1.6945x; 1.0006x over previous
#include <cuda_runtime.h>
#include <cuda_bf16.h>
#include <math.h>

#define Bsz   512
#define Tsz   256
#define Fsz   128
#define Hsz   512
#define FFsz  1024
#define OUTsz 64
#define H3    (3 * Hsz)
#define BT    (Bsz * Tsz)
#define PADV  (-999.0f)
#define GW_WORDS 24576   // per-block_n W slice (bf16): 32kt*3g*2nw*(32lane*4w) = 96KB

// ---------------- scratch ----------------
__device__ float g_GI[(size_t)BT * H3];
__device__ float g_ffin[(size_t)BT * Hsz];
__device__ float g_hid[(size_t)BT * FFsz];
// fragment-major h (bf16x2 words, kp-paired): [pp][m][kp(16)][16 words]
__device__ unsigned g_hfrag[2][(size_t)Bsz * 256];
__device__ unsigned g_wfrag[16 * GW_WORDS];
__device__ unsigned g_barg[8 * 32];   // per-m-group barrier counters (128B spaced)

// ---------------- helpers ----------------
__device__ __forceinline__ unsigned long long pack2(float x, float y) {
    unsigned long long r;
    asm("mov.b64 %0,{%1,%2};" : "=l"(r) : "f"(x), "f"(y));
    return r;
}
__device__ __forceinline__ void fma2(unsigned long long& d, unsigned long long a,
                                     unsigned long long b) {
    asm("fma.rn.f32x2 %0,%1,%2,%0;" : "+l"(d) : "l"(a), "l"(b));
}
__device__ __forceinline__ void unpack2(unsigned long long v, float& x, float& y) {
    asm("mov.b64 {%0,%1},%2;" : "=f"(x), "=f"(y) : "l"(v));
}
__device__ __forceinline__ void mma_bf16(float* d, unsigned a0, unsigned a1,
                                         unsigned a2, unsigned a3,
                                         unsigned b0, unsigned b1) {
    asm volatile(
        "mma.sync.aligned.m16n8k16.row.col.f32.bf16.bf16.f32 "
        "{%0,%1,%2,%3},{%4,%5,%6,%7},{%8,%9},{%0,%1,%2,%3};"
        : "+f"(d[0]), "+f"(d[1]), "+f"(d[2]), "+f"(d[3])
        : "r"(a0), "r"(a1), "r"(a2), "r"(a3), "r"(b0), "r"(b1));
}
__device__ __forceinline__ unsigned bf2pack(float x, float y) {
    __nv_bfloat162 v = __floats2bfloat162_rn(x, y);
    return *(unsigned*)&v;
}

// ---------------- init ----------------
__global__ void init_kernel() {
    int i = blockIdx.x * blockDim.x + threadIdx.x;
    int tot = Bsz * 256;
    if (i < tot) g_hfrag[0][i] = 0u;
    if (i < 8 * 32) g_barg[i] = 0u;
}

// ---------------- W_hh -> bf16 fragment layout ----------------
// [bn(16)][kt(32)][g(3)][nw(2)][lane(32)][4w: j0b0,j0b1,j1b0,j1b1]
__global__ void wprep_kernel(const float* __restrict__ W_hh) {
    int idx = blockIdx.x * blockDim.x + threadIdx.x;
    if (idx >= 16 * 32 * 3 * 2 * 32) return;
    int lane = idx & 31;
    int r = idx >> 5;
    int nw = r & 1; r >>= 1;
    int g = r % 3;  r /= 3;
    int kt = r & 31;
    int bn = r >> 5;
    int grp = lane >> 2, thr = lane & 3;

    unsigned w[4];
#pragma unroll
    for (int j = 0; j < 2; j++) {
        int n_row = g * Hsz + bn * 32 + nw * 16 + j * 8 + grp;
        const float* src = &W_hh[(size_t)n_row * Hsz + kt * 16 + thr * 2];
        w[j * 2 + 0] = bf2pack(src[0], src[1]);
        w[j * 2 + 1] = bf2pack(src[8], src[9]);
    }
    unsigned* dst = &g_wfrag[(size_t)(((bn * 32 + kt) * 3 + g) * 2 + nw) * 128 + lane * 4];
#pragma unroll
    for (int i = 0; i < 4; i++) dst[i] = w[i];
}

// ---------------- plain bf16 MMA GEMM (R13 version; verified) -------------------
template <int KDIM, int NDIM, bool BTRANS, bool RELU, bool SKIP>
__global__ __launch_bounds__(256) void hgemm(const float* __restrict__ A,
                                             const float* __restrict__ Bm,
                                             const float* __restrict__ bias,
                                             float* __restrict__ C,
                                             const int* __restrict__ seq) {
    const int m0 = blockIdx.x * 128;
    const int n0 = blockIdx.y * 128;
    if (SKIP) {
        int b = m0 / Tsz, t0 = m0 % Tsz;
        if (t0 >= seq[b]) return;
    }
    __shared__ __align__(16) unsigned sA[2048];
    __shared__ __align__(16) unsigned sB[2048];

    const int tid = threadIdx.x;
    const int lane = tid & 31;
    const int wid = tid >> 5;
    const int mw = wid >> 2;
    const int nw = wid & 3;
    const int grp = lane >> 2, thr = lane & 3;

    float acc[4][4][4];
#pragma unroll
    for (int i = 0; i < 4; i++)
#pragma unroll
        for (int j = 0; j < 4; j++)
#pragma unroll
            for (int c = 0; c < 4; c++) acc[i][j][c] = 0.0f;

    for (int k0 = 0; k0 < KDIM; k0 += 32) {
        if (k0 > 0) __syncthreads();
#pragma unroll
        for (int it = 0; it < 8; it++) {
            int fid = tid + it * 256;
            int row = fid >> 4, cp = fid & 15;
            int q = cp >> 3, rem = cp & 7;
            int fthr = rem & 3, whalf = rem >> 2;
            int mt = row >> 4, rin = row & 15;
            int fgrp = rin & 7, wlow = rin >> 3;
            int w = whalf * 2 + wlow;
            int flane = fgrp * 4 + fthr;
            float2 v = *(const float2*)&A[(size_t)(m0 + row) * KDIM + k0 + cp * 2];
            sA[(q * 8 + mt) * 128 + flane * 4 + w] = bf2pack(v.x, v.y);
        }
        if (BTRANS) {
#pragma unroll
            for (int it = 0; it < 8; it++) {
                int fid = tid + it * 256;
                int row = fid >> 4, cp = fid & 15;
                int q = cp >> 3, rem = cp & 7;
                int fthr = rem & 3, w = rem >> 2;
                int nt = row >> 3, fgrp = row & 7;
                int flane = fgrp * 4 + fthr;
                float2 v = *(const float2*)&Bm[(size_t)(n0 + row) * KDIM + k0 + cp * 2];
                sB[(q * 16 + nt) * 64 + flane * 2 + w] = bf2pack(v.x, v.y);
            }
        } else {
#pragma unroll
            for (int it = 0; it < 2; it++) {
                int uid = tid + it * 256;
                int kp = uid >> 5, n4 = uid & 31;
                int n = n4 * 4;
                float4 r0 = *(const float4*)&Bm[(size_t)(k0 + kp * 2) * NDIM + n0 + n];
                float4 r1 = *(const float4*)&Bm[(size_t)(k0 + kp * 2 + 1) * NDIM + n0 + n];
                int q = kp >> 3, p = kp & 7;
                int fthr = p & 3, w = p >> 2;
                float e0[4] = {r0.x, r0.y, r0.z, r0.w};
                float e1[4] = {r1.x, r1.y, r1.z, r1.w};
#pragma unroll
                for (int e = 0; e < 4; e++) {
                    int nn = n + e;
                    int nt = nn >> 3, fgrp = nn & 7;
                    int flane = fgrp * 4 + fthr;
                    sB[(q * 16 + nt) * 64 + flane * 2 + w] = bf2pack(e0[e], e1[e]);
                }
            }
        }
        __syncthreads();

#pragma unroll
        for (int q = 0; q < 2; q++) {
            uint2 bb[4];
#pragma unroll
            for (int j = 0; j < 4; j++)
                bb[j] = *(const uint2*)&sB[(q * 16 + nw * 4 + j) * 64 + lane * 2];
#pragma unroll
            for (int i = 0; i < 4; i++) {
                uint4 ah = *(const uint4*)&sA[(q * 8 + mw * 4 + i) * 128 + lane * 4];
#pragma unroll
                for (int j = 0; j < 4; j++)
                    mma_bf16(acc[i][j], ah.x, ah.y, ah.z, ah.w, bb[j].x, bb[j].y);
            }
        }
    }

#pragma unroll
    for (int i = 0; i < 4; i++) {
        const int r0 = m0 + (mw * 4 + i) * 16 + grp;
#pragma unroll
        for (int j = 0; j < 4; j++) {
            const int col = n0 + (nw * 4 + j) * 8 + thr * 2;
            const float b0 = bias[col], b1 = bias[col + 1];
            float o0 = acc[i][j][0] + b0, o1 = acc[i][j][1] + b1;
            float o2 = acc[i][j][2] + b0, o3 = acc[i][j][3] + b1;
            if (RELU) {
                o0 = fmaxf(o0, 0.f); o1 = fmaxf(o1, 0.f);
                o2 = fmaxf(o2, 0.f); o3 = fmaxf(o3, 0.f);
            }
            *(float2*)&C[(size_t)r0 * NDIM + col] = make_float2(o0, o1);
            *(float2*)&C[(size_t)(r0 + 8) * NDIM + col] = make_float2(o2, o3);
        }
    }
}

// ---------------- persistent bf16 tensor-core GRU -------------------------------
// Grid=128. Block: 64 batch x 32 hidden (x3 gates). 96KB W smem. Per kt per warp:
// 6 mma, 3 LDS.128; one LDG.128 per row per kp (2 kts). h fp32 in registers.
__global__ __launch_bounds__(256, 1) void gru_mma(
    const float* __restrict__ GI, const float* __restrict__ b_hh,
    const int* __restrict__ seq, float* __restrict__ ffin) {
    extern __shared__ unsigned Bw[];   // [kt][g][nw][lane*4] = 96KB

    const int tid = threadIdx.x;
    const int lane = tid & 31;
    const int wid  = tid >> 5;
    const int mw = wid & 3, nw = wid >> 2;
    const int grp = lane >> 2, thr = lane & 3;
    const int mgrp = blockIdx.x >> 4;
    const int m0 = mgrp * 64;
    const int block_n = blockIdx.x & 15;
    const int hb = block_n * 32;
    const int kt_g = block_n * 2 + nw;
    const int kp_g = kt_g >> 1, par_g = kt_g & 1;

    // load 96KB W slice into persistent smem
    {
        const uint4* src = (const uint4*)&g_wfrag[(size_t)block_n * GW_WORDS];
        uint4* dst = (uint4*)Bw;
        for (int i = tid; i < GW_WORDS / 4; i += 256) dst[i] = src[i];
    }

    const int m_a = m0 + mw * 16 + grp;
    const int m_b = m_a + 8;
    const int seq_a = seq[m_a];
    const int seq_b = seq[m_b];

    float2 bh[2][3];
#pragma unroll
    for (int j = 0; j < 2; j++) {
        const int hcol = hb + nw * 16 + j * 8 + thr * 2;
#pragma unroll
        for (int g = 0; g < 3; g++) bh[j][g] = *(const float2*)&b_hh[g * Hsz + hcol];
    }

    float hreg[2][2][2];   // [half][j][pair]
#pragma unroll
    for (int a = 0; a < 2; a++)
#pragma unroll
        for (int b = 0; b < 2; b++) { hreg[a][b][0] = 0.0f; hreg[a][b][1] = 0.0f; }

    __syncthreads();

    for (int t = 0; t < Tsz; ++t) {
        const int pp = t & 1;
        const unsigned* __restrict__ Af = g_hfrag[pp];
        unsigned* __restrict__ Ao = g_hfrag[pp ^ 1];

        // prefetch GI
        float2 pgi[2][2][3];
#pragma unroll
        for (int half = 0; half < 2; half++) {
            const size_t gib = ((size_t)(half ? m_b : m_a) * Tsz + t) * (size_t)H3;
#pragma unroll
            for (int j = 0; j < 2; j++) {
                const int hcol = hb + nw * 16 + j * 8 + thr * 2;
#pragma unroll
                for (int g = 0; g < 3; g++)
                    pgi[half][j][g] = *(const float2*)&GI[gib + g * Hsz + hcol];
            }
        }

        float acc[2][3][4];   // [j][g][c]
#pragma unroll
        for (int j = 0; j < 2; j++)
#pragma unroll
            for (int g = 0; g < 3; g++)
#pragma unroll
                for (int c = 0; c < 4; c++) acc[j][g][c] = 0.0f;

        // distance-2 A prefetch (per kp: one uint4 per row = 2 kt groups)
        uint4 pfA[2][2];
        const size_t abase_a = (size_t)m_a * 16;
        const size_t abase_b = (size_t)m_b * 16;
#pragma unroll
        for (int p = 0; p < 2; p++) {
            pfA[p][0] = __ldcg((const uint4*)&Af[(abase_a + p) * 16 + thr * 4]);
            pfA[p][1] = __ldcg((const uint4*)&Af[(abase_b + p) * 16 + thr * 4]);
        }

#pragma unroll 4
        for (int kp = 0; kp < 16; ++kp) {
            const uint4 arA = pfA[kp & 1][0];  // [kt0b0, kt0b1, kt1b0, kt1b1] m_a
            const uint4 arB = pfA[kp & 1][1];  // same for m_b
            if (kp < 14) {
                pfA[kp & 1][0] = __ldcg((const uint4*)&Af[(abase_a + kp + 2) * 16 + thr * 4]);
                pfA[kp & 1][1] = __ldcg((const uint4*)&Af[(abase_b + kp + 2) * 16 + thr * 4]);
            }
            // kt even
#pragma unroll
            for (int g = 0; g < 3; g++) {
                const uint4 bb = *(const uint4*)&Bw[(size_t)(((kp * 2) * 3 + g) * 2 + nw) * 128 + lane * 4];
                mma_bf16(acc[0][g], arA.x, arB.x, arA.y, arB.y, bb.x, bb.y);
                mma_bf16(acc[1][g], arA.x, arB.x, arA.y, arB.y, bb.z, bb.w);
            }
            // kt odd
#pragma unroll
            for (int g = 0; g < 3; g++) {
                const uint4 bb = *(const uint4*)&Bw[(size_t)(((kp * 2 + 1) * 3 + g) * 2 + nw) * 128 + lane * 4];
                mma_bf16(acc[0][g], arA.z, arB.z, arA.w, arB.w, bb.x, bb.y);
                mma_bf16(acc[1][g], arA.z, arB.z, arA.w, arB.w, bb.z, bb.w);
            }
        }

        // epilogue: gates + state update (h fp32 in registers)
#pragma unroll
        for (int half = 0; half < 2; half++) {
            const int m = half ? m_b : m_a;
            const int sl = half ? seq_b : seq_a;
            const int ai = half * 2;
            const size_t bt = (size_t)m * Tsz + t;
#pragma unroll
            for (int j = 0; j < 2; j++) {
                const int hcol = hb + nw * 16 + j * 8 + thr * 2;
                if (t < sl) {
                    const float ghr0 = acc[j][0][ai] + bh[j][0].x;
                    const float ghr1 = acc[j][0][ai + 1] + bh[j][0].y;
                    const float ghz0 = acc[j][1][ai] + bh[j][1].x;
                    const float ghz1 = acc[j][1][ai + 1] + bh[j][1].y;
                    const float ghn0 = acc[j][2][ai] + bh[j][2].x;
                    const float ghn1 = acc[j][2][ai + 1] + bh[j][2].y;
                    const float r0 = __fdividef(1.0f, 1.0f + __expf(-(pgi[half][j][0].x + ghr0)));
                    const float r1 = __fdividef(1.0f, 1.0f + __expf(-(pgi[half][j][0].y + ghr1)));
                    const float z0 = __fdividef(1.0f, 1.0f + __expf(-(pgi[half][j][1].x + ghz0)));
                    const float z1 = __fdividef(1.0f, 1.0f + __expf(-(pgi[half][j][1].y + ghz1)));
                    const float n0v = tanhf(pgi[half][j][2].x + r0 * ghn0);
                    const float n1v = tanhf(pgi[half][j][2].y + r1 * ghn1);
                    const float hn0 = (1.0f - z0) * n0v + z0 * hreg[half][j][0];
                    const float hn1 = (1.0f - z1) * n1v + z1 * hreg[half][j][1];
                    hreg[half][j][0] = hn0;
                    hreg[half][j][1] = hn1;
                    *(float2*)&ffin[bt * (size_t)Hsz + hcol] = make_float2(hn0, hn1);
                } else {
                    *(float2*)&ffin[bt * (size_t)Hsz + hcol] = make_float2(0.0f, 0.0f);
                }
            }
            // one uint2 store: [j0 pack, j1 pack] at kp_g / parity slot
            const size_t ab = ((size_t)m * 16 + kp_g) * 16 + thr * 4 + par_g * 2;
            uint2 st;
            st.x = bf2pack(hreg[half][0][0], hreg[half][0][1]);
            st.y = bf2pack(hreg[half][1][0], hreg[half][1][1]);
            *(uint2*)&Ao[ab] = st;
        }

        // per-m-group barrier (16 blocks)
        if (t < Tsz - 1) {
            __threadfence();
            __syncthreads();
            if (tid == 0) {
                unsigned* ctr = &g_barg[mgrp * 32];
                atomicAdd(ctr, 1u);
                const unsigned target = 16u * (unsigned)(t + 1);
                while (atomicAdd(ctr, 0u) < target) __nanosleep(32);
            }
            __syncthreads();
        }
    }
}

// ---------------- output GEMM: Y = hid @ W2 + b2, PAD-masked ---------------------
__global__ __launch_bounds__(256) void out_gemm_kernel(const float* __restrict__ W2,
                                                       const float* __restrict__ b2,
                                                       const int* __restrict__ seq,
                                                       float* __restrict__ Y) {
    const int m0 = blockIdx.x * 128;
    const int b  = m0 / Tsz;
    const int t0 = m0 % Tsz;
    const int tid = threadIdx.x;
    const int slen = seq[b];
    if (t0 >= slen) {
        float4 pv = make_float4(PADV, PADV, PADV, PADV);
#pragma unroll
        for (int l = 0; l < 8; l++) {
            int idx = tid + l * 256;
            *(float4*)&Y[(size_t)(m0 + (idx >> 4)) * OUTsz + (idx & 15) * 4] = pv;
        }
        return;
    }
    __shared__ float As[32][128];
    __shared__ float Bs[32][64];
    const int tx = tid % 16, ty = tid / 16;
    const int row0 = ty * 8, col0 = tx * 4;
    unsigned long long acc[8][2];
#pragma unroll
    for (int i = 0; i < 8; i++) { acc[i][0] = 0ULL; acc[i][1] = 0ULL; }

    for (int k0 = 0; k0 < FFsz; k0 += 32) {
#pragma unroll
        for (int l = 0; l < 4; l++) {
            int idx = tid + l * 256;
            int r = idx >> 3, c4 = (idx & 7) * 4;
            float4 v = *(const float4*)&g_hid[(size_t)(m0 + r) * FFsz + k0 + c4];
            As[c4 + 0][r] = v.x; As[c4 + 1][r] = v.y;
            As[c4 + 2][r] = v.z; As[c4 + 3][r] = v.w;
        }
#pragma unroll
        for (int l = 0; l < 2; l++) {
            int idx = tid + l * 256;
            int k = idx >> 4, c4 = (idx & 15) * 4;
            *(float4*)&Bs[k][c4] = *(const float4*)&W2[(size_t)(k0 + k) * OUTsz + c4];
        }
        __syncthreads();
#pragma unroll
        for (int k = 0; k < 32; k++) {
            float4 a0 = *(const float4*)&As[k][row0];
            float4 a1 = *(const float4*)&As[k][row0 + 4];
            unsigned long long b0 = *(const unsigned long long*)&Bs[k][col0];
            unsigned long long b1 = *(const unsigned long long*)&Bs[k][col0 + 2];
            float av[8] = {a0.x, a0.y, a0.z, a0.w, a1.x, a1.y, a1.z, a1.w};
#pragma unroll
            for (int i = 0; i < 8; i++) {
                unsigned long long ad = pack2(av[i], av[i]);
                fma2(acc[i][0], ad, b0);
                fma2(acc[i][1], ad, b1);
            }
        }
        __syncthreads();
    }
#pragma unroll
    for (int i = 0; i < 8; i++) {
        int m = m0 + row0 + i;
        int t = t0 + row0 + i;
        float o[4];
        unpack2(acc[i][0], o[0], o[1]);
        unpack2(acc[i][1], o[2], o[3]);
        float4 v;
        if (t < slen) {
            v = make_float4(o[0] + b2[col0 + 0], o[1] + b2[col0 + 1],
                            o[2] + b2[col0 + 2], o[3] + b2[col0 + 3]);
        } else {
            v = make_float4(PADV, PADV, PADV, PADV);
        }
        *(float4*)&Y[(size_t)m * OUTsz + col0] = v;
    }
}

// ---------------- launch ----------------
extern "C" void kernel_launch(void* const* d_in, const int* in_sizes, int n_in,
                              void* d_out, int out_size) {
    (void)in_sizes; (void)n_in; (void)out_size;
    const float* x    = (const float*)d_in[0];
    const int*   seq  = (const int*)d_in[1];
    const float* W_ih = (const float*)d_in[2];
    const float* W_hh = (const float*)d_in[3];
    const float* b_ih = (const float*)d_in[4];
    const float* b_hh = (const float*)d_in[5];
    const float* W1   = (const float*)d_in[6];
    const float* b1   = (const float*)d_in[7];
    const float* W2   = (const float*)d_in[8];
    const float* b2   = (const float*)d_in[9];
    float* Y = (float*)d_out;

    float *pGI = nullptr, *pFF = nullptr, *pHID = nullptr;
    cudaGetSymbolAddress((void**)&pGI, g_GI);
    cudaGetSymbolAddress((void**)&pFF, g_ffin);
    cudaGetSymbolAddress((void**)&pHID, g_hid);

    const int smem_bytes = GW_WORDS * 4;   // 98,304 B
    static bool attr_set = false;
    if (!attr_set) {
        cudaFuncSetAttribute(gru_mma, cudaFuncAttributeMaxDynamicSharedMemorySize,
                             smem_bytes);
        attr_set = true;
    }

    init_kernel<<<(Bsz * 256 + 255) / 256, 256>>>();
    wprep_kernel<<<(16 * 32 * 3 * 2 * 32 + 255) / 256, 256>>>(W_hh);

    // GI = x @ W_ih^T + b_ih   (plain bf16 mma)
    hgemm<Fsz, H3, true, false, true>
        <<<dim3(BT / 128, H3 / 128), 256>>>(x, W_ih, b_ih, pGI, seq);

    gru_mma<<<128, 256, smem_bytes>>>(pGI, b_hh, seq, pFF);

    // HID = relu(ffin @ W1 + b1)   (plain bf16 mma)
    hgemm<Hsz, FFsz, false, true, true>
        <<<dim3(BT / 128, FFsz / 128), 256>>>(pFF, W1, b1, pHID, seq);

    out_gemm_kernel<<<dim3(BT / 128), 256>>>(W2, b2, seq, Y);
}